// round 16
// baseline (speedup 1.0000x reference)
#include <cuda_runtime.h>
#include <cuda_bf16.h>
#include <cstdint>
#include <math.h>

// ---------------------------------------------------------------------------
// Arch-feature gate: tcgen05 arch-specific instrs only exist on sm_10Xa.
// The harness also compiles a plain compute_103 pass -> fallback bodies there.
// ---------------------------------------------------------------------------
#if defined(__CUDA_ARCH__)
#  if defined(__CUDA_ARCH_FEAT_SM103_ALL) || defined(__CUDA_ARCH_FEAT_SM100_ALL) || \
      defined(__CUDA_ARCH_FEAT_SM101_ALL)
#    define HAS_TCGEN05 1
#  elif defined(__CUDA_ARCH_HAS_FEATURE__)
#    if __CUDA_ARCH_HAS_FEATURE__(SM103_ALL) || __CUDA_ARCH_HAS_FEATURE__(SM100_ALL)
#      define HAS_TCGEN05 1
#    else
#      define HAS_TCGEN05 0
#    endif
#  else
#    define HAS_TCGEN05 0
#  endif
#else
#  define HAS_TCGEN05 0
#endif

// ---------------------------------------------------------------------------
// Problem constants
// ---------------------------------------------------------------------------
#define HIDDEN 2048
#define S_LEN  2048
#define NH     32
#define NKV    8
#define HD     64
#define NQD    (NH * HD)    // 2048
#define NKVD   (NKV * HD)   // 512

// ---------------------------------------------------------------------------
// Device-global scratch
// ---------------------------------------------------------------------------
__device__ float g_v  [S_LEN * NKVD];
__device__ float g_cos[S_LEN * 32];
__device__ float g_sin[S_LEN * 32];

__device__ __nv_bfloat16 g_xhi[S_LEN * HIDDEN], g_xlo[S_LEN * HIDDEN];
__device__ __nv_bfloat16 g_chi[S_LEN * NQD],    g_clo[S_LEN * NQD];
__device__ __nv_bfloat16 g_wqhi[NQD  * HIDDEN], g_wqlo[NQD  * HIDDEN]; // [N][K]
__device__ __nv_bfloat16 g_wkhi[NKVD * HIDDEN], g_wklo[NKVD * HIDDEN];
__device__ __nv_bfloat16 g_wvhi[NKVD * HIDDEN], g_wvlo[NKVD * HIDDEN];
__device__ __nv_bfloat16 g_wohi[HIDDEN * NQD],  g_wolo[HIDDEN * NQD];  // [N][K]

// attention operands (rotated; Q pre-scaled by 1/8)
__device__ __nv_bfloat16 g_qshi[S_LEN * NQD],  g_qslo[S_LEN * NQD];
__device__ __nv_bfloat16 g_kshi[S_LEN * NKVD], g_kslo[S_LEN * NKVD];
__device__ __nv_bfloat16 g_vthi[NKVD * S_LEN], g_vtlo[NKVD * S_LEN];  // [hk*64+d][t]

// ---------------------------------------------------------------------------
// PTX helpers (sm_10Xa pass only)
// ---------------------------------------------------------------------------
#if HAS_TCGEN05

__device__ __forceinline__ uint32_t smem_u32(const void* p) {
    uint32_t a;
    asm("{ .reg .u64 t; cvta.to.shared.u64 t, %1; cvt.u32.u64 %0, t; }"
        : "=r"(a) : "l"(p));
    return a;
}

__device__ __forceinline__ uint32_t elect_one() {
    uint32_t pred;
    asm volatile("{ .reg .pred p; elect.sync _|p, 0xFFFFFFFF; selp.b32 %0, 1, 0, p; }"
                 : "=r"(pred));
    return pred;
}

#define MBARRIER_INIT(addr, cnt) \
    asm volatile("mbarrier.init.shared.b64 [%0], %1;" :: "r"(addr), "r"(cnt) : "memory")

#define MBARRIER_WAIT_PARITY(mbar, par) do {                                          \
    uint32_t _m = (mbar); uint32_t _p = (par); uint32_t _done;                        \
    asm volatile("{ .reg .pred p; mbarrier.try_wait.parity.acquire.cta.shared::cta.b64 p, [%1], %2;" \
                 " selp.b32 %0, 1, 0, p; }" : "=r"(_done) : "r"(_m), "r"(_p) : "memory"); \
    if (!_done) {                                                                     \
        asm volatile("{ .reg .pred P1; WAIT_LOOP_%=:"                                 \
            " mbarrier.try_wait.parity.acquire.cta.shared::cta.b64 P1, [%0], %1, 0x989680;" \
            " @P1 bra.uni WAIT_DONE_%=; bra.uni WAIT_LOOP_%=; WAIT_DONE_%=: }"        \
            :: "r"(_m), "r"(_p) : "memory");                                          \
    }                                                                                 \
} while (0)

#define TCGEN05_ALLOC(sm_addr, ncols) \
    asm volatile("tcgen05.alloc.cta_group::1.sync.aligned.shared::cta.b32 [%0], %1;" \
                 :: "r"(sm_addr), "r"(ncols) : "memory")
#define TCGEN05_DEALLOC(tm, ncols) \
    asm volatile("tcgen05.dealloc.cta_group::1.sync.aligned.b32 %0, %1;" :: "r"(tm), "r"(ncols))
#define TCGEN05_RELINQ() \
    asm volatile("tcgen05.relinquish_alloc_permit.cta_group::1.sync.aligned;")
#define TCGEN05_COMMIT(mbar) \
    asm volatile("tcgen05.commit.cta_group::1.mbarrier::arrive::one.shared::cluster.b64 [%0];" \
                 :: "r"(mbar) : "memory")
#define TCGEN05_WAIT_LD() asm volatile("tcgen05.wait::ld.sync.aligned;" ::: "memory")
#define TCGEN05_FENCE_AFTER()  asm volatile("tcgen05.fence::after_thread_sync;" ::: "memory")
#define TCGEN05_FENCE_BEFORE() asm volatile("tcgen05.fence::before_thread_sync;" ::: "memory")
#define FENCE_ASYNC() asm volatile("fence.proxy.async.shared::cta;" ::: "memory")

#define CP_COMMIT() asm volatile("cp.async.commit_group;" ::: "memory")
#define CP_WAIT1()  asm volatile("cp.async.wait_group 1;" ::: "memory")
#define CP_WAIT0()  asm volatile("cp.async.wait_group 0;" ::: "memory")

#define TCGEN05_LD_X32(r, tm) \
    asm volatile( \
        "tcgen05.ld.sync.aligned.32x32b.x32.b32 " \
        "{%0, %1, %2, %3, %4, %5, %6, %7, %8, %9, %10, %11, %12, %13, %14, %15, " \
        " %16, %17, %18, %19, %20, %21, %22, %23, %24, %25, %26, %27, %28, %29, %30, %31}, [%32];" \
        : "=r"((r)[0]),  "=r"((r)[1]),  "=r"((r)[2]),  "=r"((r)[3]), \
          "=r"((r)[4]),  "=r"((r)[5]),  "=r"((r)[6]),  "=r"((r)[7]), \
          "=r"((r)[8]),  "=r"((r)[9]),  "=r"((r)[10]), "=r"((r)[11]), \
          "=r"((r)[12]), "=r"((r)[13]), "=r"((r)[14]), "=r"((r)[15]), \
          "=r"((r)[16]), "=r"((r)[17]), "=r"((r)[18]), "=r"((r)[19]), \
          "=r"((r)[20]), "=r"((r)[21]), "=r"((r)[22]), "=r"((r)[23]), \
          "=r"((r)[24]), "=r"((r)[25]), "=r"((r)[26]), "=r"((r)[27]), \
          "=r"((r)[28]), "=r"((r)[29]), "=r"((r)[30]), "=r"((r)[31]) \
        : "r"(tm))

__device__ __forceinline__ uint64_t make_desc_sw128(uint32_t addr) {
    return (uint64_t(2) << 61) | (uint64_t(1) << 46) | (uint64_t(64) << 32) |
           (uint64_t(1) << 16) | ((uint64_t)(addr >> 4) & 0x3FFF);
}

__device__ __forceinline__ void mma_bf16_ss(uint32_t d_tmem, uint64_t a_desc,
                                            uint64_t b_desc, uint32_t idesc, uint32_t en) {
    asm volatile(
        "{\n\t.reg .pred p;\n\t"
        "setp.ne.u32 p, %5, 0;\n\t"
        "tcgen05.mma.cta_group::1.kind::f16 [%0], %1, %2, %3, {%4, %4, %4, %4}, p;\n\t"
        "}"
        :: "r"(d_tmem), "l"(a_desc), "l"(b_desc), "r"(idesc), "r"(0u), "r"(en)
        : "memory");
}

#define GEMM_IDESC ((1u << 4) | (1u << 7) | (1u << 10) | ((128u / 8u) << 17) | ((128u / 16u) << 24))
#define PV_IDESC   ((1u << 4) | (1u << 7) | (1u << 10) | ((64u  / 8u) << 17) | ((128u / 16u) << 24))

#endif  // HAS_TCGEN05

// ---------------------------------------------------------------------------
// Conversion / prep kernels
// ---------------------------------------------------------------------------
__global__ void convert_split_kernel(const float4* __restrict__ in,
                                     uint2* __restrict__ hi,
                                     uint2* __restrict__ lo, int n4)
{
    int i = blockIdx.x * blockDim.x + threadIdx.x;
    if (i >= n4) return;
    float4 x = in[i];
    __nv_bfloat16 h0 = __float2bfloat16(x.x), h1 = __float2bfloat16(x.y);
    __nv_bfloat16 h2 = __float2bfloat16(x.z), h3 = __float2bfloat16(x.w);
    __nv_bfloat16 l0 = __float2bfloat16(x.x - __bfloat162float(h0));
    __nv_bfloat16 l1 = __float2bfloat16(x.y - __bfloat162float(h1));
    __nv_bfloat16 l2 = __float2bfloat16(x.z - __bfloat162float(h2));
    __nv_bfloat16 l3 = __float2bfloat16(x.w - __bfloat162float(h3));
    uint2 ho, loo;
    ho.x  = (uint32_t)__bfloat16_as_ushort(h0) | ((uint32_t)__bfloat16_as_ushort(h1) << 16);
    ho.y  = (uint32_t)__bfloat16_as_ushort(h2) | ((uint32_t)__bfloat16_as_ushort(h3) << 16);
    loo.x = (uint32_t)__bfloat16_as_ushort(l0) | ((uint32_t)__bfloat16_as_ushort(l1) << 16);
    loo.y = (uint32_t)__bfloat16_as_ushort(l2) | ((uint32_t)__bfloat16_as_ushort(l3) << 16);
    hi[i] = ho;
    lo[i] = loo;
}

__global__ void convert_wT_kernel(const float* __restrict__ W,
                                  __nv_bfloat16* __restrict__ hi,
                                  __nv_bfloat16* __restrict__ lo, int K, int N)
{
    __shared__ float t[32][33];
    int n0 = blockIdx.x * 32, k0 = blockIdx.y * 32;
    int tx = threadIdx.x, ty = threadIdx.y;  // block (32, 8)
#pragma unroll
    for (int i = ty; i < 32; i += 8)
        t[i][tx] = W[(size_t)(k0 + i) * N + n0 + tx];
    __syncthreads();
#pragma unroll
    for (int i = ty; i < 32; i += 8) {
        float x = t[tx][i];
        __nv_bfloat16 h = __float2bfloat16(x);
        size_t o = (size_t)(n0 + i) * K + k0 + tx;
        hi[o] = h;
        lo[o] = __float2bfloat16(x - __bfloat162float(h));
    }
}

// RoPE tables. sincosf is (x, &sin, &cos) — SIN FIRST.
__global__ void rope_table_kernel()
{
    int idx = blockIdx.x * blockDim.x + threadIdx.x;
    if (idx >= S_LEN * 32) return;
    int p = idx & 31;
    int t = idx >> 5;
    float inv_freq = (float)exp(-((double)(2 * p) / 64.0) * log(10000.0));
    float ang = (float)t * inv_freq;
    float s, c;
    sincosf(ang, &s, &c);
    g_cos[idx] = c;
    g_sin[idx] = s;
}

__global__ void prep_vt_kernel(const float* __restrict__ V,
                               __nv_bfloat16* __restrict__ hi,
                               __nv_bfloat16* __restrict__ lo)
{
    __shared__ float tile[32][33];
    int c0 = blockIdx.x * 32;
    int t0 = blockIdx.y * 32;
    int tx = threadIdx.x, ty = threadIdx.y;  // (32, 8)
#pragma unroll
    for (int i = ty; i < 32; i += 8)
        tile[i][tx] = V[(size_t)(t0 + i) * NKVD + c0 + tx];
    __syncthreads();
#pragma unroll
    for (int i = ty; i < 32; i += 8) {
        float x = tile[tx][i];
        __nv_bfloat16 h = __float2bfloat16(x);
        size_t o = (size_t)(c0 + i) * S_LEN + t0 + tx;
        hi[o] = h;
        lo[o] = __float2bfloat16(x - __bfloat162float(h));
    }
}

// ---------------------------------------------------------------------------
// tcgen05 split-bf16 GEMM mainloop (R12-proven): cp.async 3-stage pipeline,
// 2 MMA chunks in flight. Two kernels share it:
//   tc_gemm_kernel     — fp32 C output (used for Wo)
//   tc_gemm_qkv_kernel — fused Q/K/V: bx selects matrix; Q/K get RoPE+scale+
//                        split epilogue (vectorized), V writes fp32.
// ---------------------------------------------------------------------------
#define GK 64
#define TILE_B (128 * GK * 2)
#define STAGE_B (4 * TILE_B)
#define GEMM_SMEM (2048 + 3 * STAGE_B)   // 198656 B

#if HAS_TCGEN05
__device__ __forceinline__ void load_tile_cpasync(uint32_t sdst,
                                                  const __nv_bfloat16* __restrict__ g,
                                                  int row0, int ld, int k0, int tid)
{
    const char* gb = (const char*)(g + (size_t)row0 * ld + k0);
#pragma unroll
    for (int i = 0; i < 4; i++) {
        int v  = i * 256 + tid;          // 0..1023 vectors of 16B
        int r  = v >> 3;                 // row 0..127
        int vc = (v & 7) << 4;           // byte col 0..112
        uint32_t off = r * 128 + vc;
        uint32_t swo = off ^ ((off >> 3) & 0x70);
        asm volatile("cp.async.cg.shared.global [%0], [%1], 16;"
                     :: "r"(sdst + swo), "l"(gb + (size_t)r * (ld * 2) + vc));
    }
}

// Shared mainloop: accumulate A[m0:m0+128, :] @ B[n0:n0+128, :]^T into TMEM.
__device__ __forceinline__ void gemm_mainloop(
    uint32_t sb, uint32_t tbase, uint32_t tmem,
    const __nv_bfloat16* __restrict__ Ahi, const __nv_bfloat16* __restrict__ Alo,
    const __nv_bfloat16* __restrict__ Bhi, const __nv_bfloat16* __restrict__ Blo,
    int m0, int n0, int K, int tid, int wid)
{
    const uint32_t BAR0 = sb, BAR1 = sb + 8;
    const int nchunks = K / GK;

    {
        uint32_t sa = tbase;
        load_tile_cpasync(sa + 0 * TILE_B, Ahi, m0, K, 0, tid);
        load_tile_cpasync(sa + 1 * TILE_B, Alo, m0, K, 0, tid);
        load_tile_cpasync(sa + 2 * TILE_B, Bhi, n0, K, 0, tid);
        load_tile_cpasync(sa + 3 * TILE_B, Blo, n0, K, 0, tid);
        CP_COMMIT();
    }
    if (nchunks > 1) {
        uint32_t sa = tbase + STAGE_B;
        load_tile_cpasync(sa + 0 * TILE_B, Ahi, m0, K, GK, tid);
        load_tile_cpasync(sa + 1 * TILE_B, Alo, m0, K, GK, tid);
        load_tile_cpasync(sa + 2 * TILE_B, Bhi, n0, K, GK, tid);
        load_tile_cpasync(sa + 3 * TILE_B, Blo, n0, K, GK, tid);
    }
    CP_COMMIT();

    int ph0 = 0, ph1 = 0;
    for (int c = 0; c < nchunks; c++) {
        CP_WAIT1();
        FENCE_ASYNC();
        __syncthreads();

        if (wid == 0 && elect_one()) {
            const uint32_t sa = tbase + (uint32_t)(c % 3) * STAGE_B;
            uint64_t dAhi = make_desc_sw128(sa + 0 * TILE_B);
            uint64_t dAlo = make_desc_sw128(sa + 1 * TILE_B);
            uint64_t dBhi = make_desc_sw128(sa + 2 * TILE_B);
            uint64_t dBlo = make_desc_sw128(sa + 3 * TILE_B);
            uint64_t da[3] = { dAhi, dAhi, dAlo };
            uint64_t db[3] = { dBhi, dBlo, dBhi };
#pragma unroll
            for (int t = 0; t < 3; t++)
#pragma unroll
                for (int ks = 0; ks < 4; ks++)
                    mma_bf16_ss(tmem, da[t] + ks * 2, db[t] + ks * 2, GEMM_IDESC,
                                (c | t | ks) ? 1u : 0u);
            TCGEN05_COMMIT((c & 1) ? BAR1 : BAR0);
        }

        if (c >= 1) {
            if ((c - 1) & 1) { MBARRIER_WAIT_PARITY(BAR1, ph1); ph1 ^= 1; }
            else             { MBARRIER_WAIT_PARITY(BAR0, ph0); ph0 ^= 1; }
        }

        if (c + 2 < nchunks) {
            uint32_t sa = tbase + (uint32_t)((c + 2) % 3) * STAGE_B;
            const int k2 = (c + 2) * GK;
            load_tile_cpasync(sa + 0 * TILE_B, Ahi, m0, K, k2, tid);
            load_tile_cpasync(sa + 1 * TILE_B, Alo, m0, K, k2, tid);
            load_tile_cpasync(sa + 2 * TILE_B, Bhi, n0, K, k2, tid);
            load_tile_cpasync(sa + 3 * TILE_B, Blo, n0, K, k2, tid);
        }
        CP_COMMIT();
    }

    if ((nchunks - 1) & 1) { MBARRIER_WAIT_PARITY(BAR1, ph1); }
    else                   { MBARRIER_WAIT_PARITY(BAR0, ph0); }
    TCGEN05_FENCE_AFTER();
}
#endif

// Wo projection: fp32 C output (unchanged R12 behavior).
__global__ __launch_bounds__(256, 1) void tc_gemm_kernel(
    const __nv_bfloat16* __restrict__ Ahi, const __nv_bfloat16* __restrict__ Alo,
    const __nv_bfloat16* __restrict__ Bhi, const __nv_bfloat16* __restrict__ Blo,
    float* __restrict__ C, int M, int N, int K)
{
#if HAS_TCGEN05
    extern __shared__ char smem[];
    const uint32_t sb = smem_u32(smem);
    const int tid = threadIdx.x;
    const int wid = tid >> 5;
    const int lid = tid & 31;
    const int m0 = blockIdx.y * 128;
    const int n0 = blockIdx.x * 128;
    const uint32_t TPTR = sb + 16;
    const uint32_t tbase = (sb + 24 + 1023) & ~1023u;

    if (wid == 0) TCGEN05_ALLOC(TPTR, 128);
    if (tid == 0) { MBARRIER_INIT(sb, 1); MBARRIER_INIT(sb + 8, 1); }
    __syncthreads();
    uint32_t tmem;
    asm volatile("ld.shared.b32 %0, [%1];" : "=r"(tmem) : "r"(TPTR));

    gemm_mainloop(sb, tbase, tmem, Ahi, Alo, Bhi, Blo, m0, n0, K, tid, wid);

    if (wid < 4) {
        const int m = m0 + wid * 32 + lid;
        float* crow = C + (size_t)m * N + n0;
#pragma unroll
        for (int nb = 0; nb < 4; nb++) {
            uint32_t dreg[32];
            TCGEN05_LD_X32(dreg, tmem + nb * 32);
            TCGEN05_WAIT_LD();
            TCGEN05_FENCE_BEFORE();
            float4* dst = reinterpret_cast<float4*>(crow + nb * 32);
#pragma unroll
            for (int j = 0; j < 8; j++)
                dst[j] = make_float4(__uint_as_float(dreg[4 * j + 0]),
                                     __uint_as_float(dreg[4 * j + 1]),
                                     __uint_as_float(dreg[4 * j + 2]),
                                     __uint_as_float(dreg[4 * j + 3]));
        }
    }
    __syncthreads();
    if (wid == 0) { TCGEN05_RELINQ(); TCGEN05_DEALLOC(tmem, 128); }

#else  // FFMA fallback (plain pass; never selected at runtime)
    __shared__ float As[64][33];
    __shared__ float Bs[64][33];
    const int tid = threadIdx.x;
    const int tx  = tid & 15;
    const int ty  = tid >> 4;
    for (int sub = 0; sub < 4; sub++) {
        const int m0 = blockIdx.y * 128 + (sub >> 1) * 64;
        const int n0 = blockIdx.x * 128 + (sub & 1) * 64;
        float acc[4][4] = {};
        for (int k0 = 0; k0 < K; k0 += 32) {
            __syncthreads();
#pragma unroll
            for (int i = 0; i < 8; i++) {
                int e  = tid * 8 + i;
                int r  = e >> 5;
                int kk = e & 31;
                size_t ai = (size_t)(m0 + r) * K + k0 + kk;
                size_t bi = (size_t)(n0 + r) * K + k0 + kk;
                As[r][kk] = __bfloat162float(Ahi[ai]) + __bfloat162float(Alo[ai]);
                Bs[r][kk] = __bfloat162float(Bhi[bi]) + __bfloat162float(Blo[bi]);
            }
            __syncthreads();
#pragma unroll
            for (int k = 0; k < 32; k++) {
                float a[4], b[4];
#pragma unroll
                for (int i = 0; i < 4; i++) a[i] = As[ty * 4 + i][k];
#pragma unroll
                for (int j = 0; j < 4; j++) b[j] = Bs[tx * 4 + j][k];
#pragma unroll
                for (int i = 0; i < 4; i++)
#pragma unroll
                    for (int j = 0; j < 4; j++) acc[i][j] += a[i] * b[j];
            }
        }
        __syncthreads();
#pragma unroll
        for (int i = 0; i < 4; i++) {
            float4 r = make_float4(acc[i][0], acc[i][1], acc[i][2], acc[i][3]);
            *reinterpret_cast<float4*>(C + (size_t)(m0 + ty * 4 + i) * N + n0 + tx * 4) = r;
        }
    }
#endif
}

// Fused Q/K/V projections. grid = (24, 16): bx 0-15 Wq (rope, scale 1/8),
// bx 16-19 Wk (rope, scale 1), bx 20-23 Wv (fp32 out).
__global__ __launch_bounds__(256, 1) void tc_gemm_qkv_kernel(
    const __nv_bfloat16* __restrict__ xhi, const __nv_bfloat16* __restrict__ xlo,
    const __nv_bfloat16* __restrict__ wqh, const __nv_bfloat16* __restrict__ wql,
    const __nv_bfloat16* __restrict__ wkh, const __nv_bfloat16* __restrict__ wkl,
    const __nv_bfloat16* __restrict__ wvh, const __nv_bfloat16* __restrict__ wvl,
    __nv_bfloat16* __restrict__ qsh, __nv_bfloat16* __restrict__ qsl,
    __nv_bfloat16* __restrict__ ksh, __nv_bfloat16* __restrict__ ksl,
    float* __restrict__ vout)
{
    const int bx = blockIdx.x;
    const __nv_bfloat16 *Bhi, *Blo;
    __nv_bfloat16 *Ohi = nullptr, *Olo = nullptr;
    int n0, ldC, mode;
    float scale = 1.0f;
    if (bx < 16)      { Bhi = wqh; Blo = wql; n0 = bx * 128;        ldC = NQD;  mode = 1;
                        scale = 0.125f; Ohi = qsh; Olo = qsl; }
    else if (bx < 20) { Bhi = wkh; Blo = wkl; n0 = (bx - 16) * 128; ldC = NKVD; mode = 1;
                        Ohi = ksh; Olo = ksl; }
    else              { Bhi = wvh; Blo = wvl; n0 = (bx - 20) * 128; ldC = NKVD; mode = 0; }

#if HAS_TCGEN05
    extern __shared__ char smem[];
    const uint32_t sb = smem_u32(smem);
    const int tid = threadIdx.x;
    const int wid = tid >> 5;
    const int lid = tid & 31;
    const int m0 = blockIdx.y * 128;
    const uint32_t TPTR = sb + 16;
    const uint32_t tbase = (sb + 24 + 1023) & ~1023u;

    if (wid == 0) TCGEN05_ALLOC(TPTR, 128);
    if (tid == 0) { MBARRIER_INIT(sb, 1); MBARRIER_INIT(sb + 8, 1); }
    __syncthreads();
    uint32_t tmem;
    asm volatile("ld.shared.b32 %0, [%1];" : "=r"(tmem) : "r"(TPTR));

    gemm_mainloop(sb, tbase, tmem, xhi, xlo, Bhi, Blo, m0, n0, HIDDEN, tid, wid);

    if (wid < 4) {
        const int m = m0 + wid * 32 + lid;   // token index
#pragma unroll
        for (int nb = 0; nb < 4; nb++) {
            uint32_t dreg[32];
            TCGEN05_LD_X32(dreg, tmem + nb * 32);
            TCGEN05_WAIT_LD();
            TCGEN05_FENCE_BEFORE();
            const int gbase = n0 + nb * 32;
            if (mode == 0) {
                float4* dst = reinterpret_cast<float4*>(vout + (size_t)m * ldC + gbase);
#pragma unroll
                for (int j = 0; j < 8; j++)
                    dst[j] = make_float4(__uint_as_float(dreg[4 * j + 0]),
                                         __uint_as_float(dreg[4 * j + 1]),
                                         __uint_as_float(dreg[4 * j + 2]),
                                         __uint_as_float(dreg[4 * j + 3]));
            } else {
                // RoPE (t = m) + scale + split; vectorized uint4 stores.
                uint4* hdst = reinterpret_cast<uint4*>(Ohi + (size_t)m * ldC + gbase);
                uint4* ldst = reinterpret_cast<uint4*>(Olo + (size_t)m * ldC + gbase);
#pragma unroll
                for (int j = 0; j < 4; j++) {
                    uint32_t hw[4], lw[4];
#pragma unroll
                    for (int w = 0; w < 4; w++) {
                        const int u = 4 * j + w;            // pair index 0..15
                        const int g = gbase + 2 * u;
                        const int p = (g & 63) >> 1;
                        float cn = g_cos[m * 32 + p];
                        float sn = g_sin[m * 32 + p];
                        float xe = __uint_as_float(dreg[2 * u]);
                        float xo = __uint_as_float(dreg[2 * u + 1]);
                        float ye = (xe * cn - xo * sn) * scale;
                        float yo = (xe * sn + xo * cn) * scale;
                        __nv_bfloat16 he = __float2bfloat16(ye);
                        __nv_bfloat16 ho = __float2bfloat16(yo);
                        __nv_bfloat16 le = __float2bfloat16(ye - __bfloat162float(he));
                        __nv_bfloat16 lo2 = __float2bfloat16(yo - __bfloat162float(ho));
                        hw[w] = (uint32_t)__bfloat16_as_ushort(he) |
                                ((uint32_t)__bfloat16_as_ushort(ho) << 16);
                        lw[w] = (uint32_t)__bfloat16_as_ushort(le) |
                                ((uint32_t)__bfloat16_as_ushort(lo2) << 16);
                    }
                    hdst[j] = make_uint4(hw[0], hw[1], hw[2], hw[3]);
                    ldst[j] = make_uint4(lw[0], lw[1], lw[2], lw[3]);
                }
            }
        }
    }
    __syncthreads();
    if (wid == 0) { TCGEN05_RELINQ(); TCGEN05_DEALLOC(tmem, 128); }

#else  // FFMA fallback (plain pass; never selected at runtime)
    __shared__ float As[64][33];
    __shared__ float Bs[64][33];
    const int tid = threadIdx.x;
    const int tx  = tid & 15;
    const int ty  = tid >> 4;
    const int K = HIDDEN;
    for (int sub = 0; sub < 4; sub++) {
        const int m0s = blockIdx.y * 128 + (sub >> 1) * 64;
        const int n0s = n0 + (sub & 1) * 64;
        float acc[4][4] = {};
        for (int k0 = 0; k0 < K; k0 += 32) {
            __syncthreads();
#pragma unroll
            for (int i = 0; i < 8; i++) {
                int e  = tid * 8 + i;
                int r  = e >> 5;
                int kk = e & 31;
                size_t ai = (size_t)(m0s + r) * K + k0 + kk;
                size_t bi = (size_t)(n0s + r) * K + k0 + kk;
                As[r][kk] = __bfloat162float(xhi[ai]) + __bfloat162float(xlo[ai]);
                Bs[r][kk] = __bfloat162float(Bhi[bi]) + __bfloat162float(Blo[bi]);
            }
            __syncthreads();
#pragma unroll
            for (int k = 0; k < 32; k++) {
                float a[4], b[4];
#pragma unroll
                for (int i = 0; i < 4; i++) a[i] = As[ty * 4 + i][k];
#pragma unroll
                for (int j = 0; j < 4; j++) b[j] = Bs[tx * 4 + j][k];
#pragma unroll
                for (int i = 0; i < 4; i++)
#pragma unroll
                    for (int j = 0; j < 4; j++) acc[i][j] += a[i] * b[j];
            }
        }
        __syncthreads();
#pragma unroll
        for (int i = 0; i < 4; i++) {
            const int m = m0s + ty * 4 + i;
            if (mode == 0) {
                float4 r = make_float4(acc[i][0], acc[i][1], acc[i][2], acc[i][3]);
                *reinterpret_cast<float4*>(vout + (size_t)m * ldC + n0s + tx * 4) = r;
            } else {
#pragma unroll
                for (int u = 0; u < 2; u++) {
                    int g = n0s + tx * 4 + 2 * u;
                    int p = (g & 63) >> 1;
                    float cn = g_cos[m * 32 + p], sn = g_sin[m * 32 + p];
                    float xe = acc[i][2 * u], xo = acc[i][2 * u + 1];
                    float ye = (xe * cn - xo * sn) * scale;
                    float yo = (xe * sn + xo * cn) * scale;
                    __nv_bfloat16 he = __float2bfloat16(ye);
                    __nv_bfloat16 ho = __float2bfloat16(yo);
                    Ohi[(size_t)m * ldC + g]     = he;
                    Ohi[(size_t)m * ldC + g + 1] = ho;
                    Olo[(size_t)m * ldC + g]     = __float2bfloat16(ye - __bfloat162float(he));
                    Olo[(size_t)m * ldC + g + 1] = __float2bfloat16(yo - __bfloat162float(ho));
                }
            }
        }
    }
#endif
}

// ---------------------------------------------------------------------------
// tcgen05 flash attention (R15-proven, unchanged): cp.async loads, split
// barriers, issue-ahead QK, split-bf16 P, 3-term PV, vectorized split-ctx
// epilogue.
// ---------------------------------------------------------------------------
#define A_QHI   0
#define A_QLO   16384
#define A_K     32768                   // Khi at +0, Klo at +16384
#define A_V(b)  (65536 + (b) * 32768)   // Vhi halves +0/+8192, Vlo +16384/+24576
#define A_PHI   131072                  // two col-halves 16K each
#define A_PLO   163840
#define A_TILES_BYTES 196608
#define ATT_SMEM (2112 + 1024 + A_TILES_BYTES)

__global__ __launch_bounds__(256, 1) void attn_tc_kernel(
    const __nv_bfloat16* __restrict__ Qhi, const __nv_bfloat16* __restrict__ Qlo,
    const __nv_bfloat16* __restrict__ Khi, const __nv_bfloat16* __restrict__ Klo,
    const __nv_bfloat16* __restrict__ Vthi, const __nv_bfloat16* __restrict__ Vtlo,
    __nv_bfloat16* __restrict__ Ohi, __nv_bfloat16* __restrict__ Olo)
{
#if HAS_TCGEN05
    extern __shared__ char smem[];
    const uint32_t sb = smem_u32(smem);
    const int tid = threadIdx.x;
    const int wid = tid >> 5;
    const int lid = tid & 31;
    const int h   = blockIdx.y;
    const int q0  = blockIdx.x * 128;
    const int hk  = h >> 2;

    const uint32_t SBAR = sb, PVBAR = sb + 8, TPTR = sb + 16;
    float* lpart = reinterpret_cast<float*>(smem + 32);   // [2][128]
    const uint32_t tbase = (sb + 32 + 1024 + 1023) & ~1023u;
    char* tgen = smem + (tbase - sb);

    if (wid == 0) TCGEN05_ALLOC(TPTR, 512);
    if (tid == 0) { MBARRIER_INIT(SBAR, 1); MBARRIER_INIT(PVBAR, 1); }
    __syncthreads();
    uint32_t tmem;
    asm volatile("ld.shared.b32 %0, [%1];" : "=r"(tmem) : "r"(TPTR));
    const uint32_t tm_S0 = tmem;
    const uint32_t tm_S1 = tmem + 128;
    const uint32_t tm_O  = tmem + 256;

    uint64_t dQhi = make_desc_sw128(tbase + A_QHI);
    uint64_t dQlo = make_desc_sw128(tbase + A_QLO);
    uint64_t dKh  = make_desc_sw128(tbase + A_K);
    uint64_t dKl  = make_desc_sw128(tbase + A_K + 16384);

    // ---- prologue: Q, K(0), V(0) (plain stores) ----
    {
        const char* ghi = (const char*)(Qhi + (size_t)q0 * NQD + h * HD);
        const char* glo = (const char*)(Qlo + (size_t)q0 * NQD + h * HD);
#pragma unroll
        for (int i = 0; i < 4; i++) {
            int v = i * 256 + tid;
            int r = v >> 3;
            int vc = (v & 7) << 4;
            uint32_t off = r * 128 + vc;
            uint32_t swo = off ^ ((off >> 3) & 0x70);
            *reinterpret_cast<uint4*>(tgen + A_QHI + swo) =
                *reinterpret_cast<const uint4*>(ghi + (size_t)r * (NQD * 2) + vc);
            *reinterpret_cast<uint4*>(tgen + A_QLO + swo) =
                *reinterpret_cast<const uint4*>(glo + (size_t)r * (NQD * 2) + vc);
        }
    }
    {
        const char* ghi = (const char*)(Khi + (size_t)0 * NKVD + hk * HD);
        const char* glo = (const char*)(Klo + (size_t)0 * NKVD + hk * HD);
#pragma unroll
        for (int i = 0; i < 4; i++) {
            int v = i * 256 + tid;
            int r = v >> 3;
            int vc = (v & 7) << 4;
            uint32_t off = r * 128 + vc;
            uint32_t swo = off ^ ((off >> 3) & 0x70);
            *reinterpret_cast<uint4*>(tgen + A_K + swo) =
                *reinterpret_cast<const uint4*>(ghi + (size_t)r * (NKVD * 2) + vc);
            *reinterpret_cast<uint4*>(tgen + A_K + 16384 + swo) =
                *reinterpret_cast<const uint4*>(glo + (size_t)r * (NKVD * 2) + vc);
        }
    }
    {
        const char* ghi = (const char*)(Vthi + (size_t)hk * HD * S_LEN + 0);
        const char* glo = (const char*)(Vtlo + (size_t)hk * HD * S_LEN + 0);
        char* vdst = tgen + A_V(0);
#pragma unroll
        for (int i = 0; i < 4; i++) {
            int v = i * 256 + tid;
            int hf = v >> 9;
            int w  = v & 511;
            int d  = w >> 3;
            int vc = (w & 7) << 4;
            uint32_t off = d * 128 + vc;
            uint32_t swo = off ^ ((off >> 3) & 0x70);
            size_t gof = (size_t)d * (S_LEN * 2) + hf * 128 + vc;
            *reinterpret_cast<uint4*>(vdst + hf * 8192 + swo) =
                *reinterpret_cast<const uint4*>(ghi + gof);
            *reinterpret_cast<uint4*>(vdst + 16384 + hf * 8192 + swo) =
                *reinterpret_cast<const uint4*>(glo + gof);
        }
    }
    FENCE_ASYNC();
    __syncthreads();

    // QK(0) -> S0, commit SBAR
    if (wid == 0 && elect_one()) {
        uint64_t da[3] = { dQhi, dQhi, dQlo };
        uint64_t db[3] = { dKh, dKl, dKh };
#pragma unroll
        for (int t = 0; t < 3; t++)
#pragma unroll
            for (int ks = 0; ks < 4; ks++)
                mma_bf16_ss(tm_S0, da[t] + ks * 2, db[t] + ks * 2, GEMM_IDESC,
                            (t | ks) ? 1u : 0u);
        TCGEN05_COMMIT(SBAR);
    }

    const int srow  = (wid & 3) * 32 + lid;
    const int chalf = wid >> 2;
    float l_part = 0.f;
    int ph_s = 0, ph_pv = 0;
    const int NIT = S_LEN / 128;

    for (int it = 0; it < NIT; it++) {
        MBARRIER_WAIT_PARITY(SBAR, ph_s); ph_s ^= 1;
        if (it > 0) { MBARRIER_WAIT_PARITY(PVBAR, ph_pv); ph_pv ^= 1; }
        TCGEN05_FENCE_AFTER();

        if (it + 1 < NIT) {
            const int c1 = (it + 1) * 128;
            const int b1 = (it + 1) & 1;
            load_tile_cpasync(tbase + A_K,         Khi, c1, NKVD, hk * HD, tid);
            load_tile_cpasync(tbase + A_K + 16384, Klo, c1, NKVD, hk * HD, tid);
            {
                const char* ghi = (const char*)(Vthi + (size_t)hk * HD * S_LEN + c1);
                const char* glo = (const char*)(Vtlo + (size_t)hk * HD * S_LEN + c1);
                const uint32_t vdst = tbase + A_V(b1);
#pragma unroll
                for (int i = 0; i < 4; i++) {
                    int v = i * 256 + tid;
                    int hf = v >> 9;
                    int w  = v & 511;
                    int d  = w >> 3;
                    int vc = (w & 7) << 4;
                    uint32_t off = d * 128 + vc;
                    uint32_t swo = off ^ ((off >> 3) & 0x70);
                    size_t gof = (size_t)d * (S_LEN * 2) + hf * 128 + vc;
                    asm volatile("cp.async.cg.shared.global [%0], [%1], 16;"
                                 :: "r"(vdst + hf * 8192 + swo), "l"(ghi + gof));
                    asm volatile("cp.async.cg.shared.global [%0], [%1], 16;"
                                 :: "r"(vdst + 16384 + hf * 8192 + swo), "l"(glo + gof));
                }
            }
        }
        CP_COMMIT();

        const uint32_t tm_Sc = (it & 1) ? tm_S1 : tm_S0;
#pragma unroll
        for (int ch = 0; ch < 2; ch++) {
            uint32_t sreg[32];
            TCGEN05_LD_X32(sreg, tm_Sc + chalf * 64 + ch * 32);
            TCGEN05_WAIT_LD();
            uint32_t hp[16], lp[16];
            float lsum = 0.f;
#pragma unroll
            for (int j = 0; j < 16; j++) {
                float p0 = __expf(__uint_as_float(sreg[2 * j]));
                float p1 = __expf(__uint_as_float(sreg[2 * j + 1]));
                lsum += p0 + p1;
                __nv_bfloat16 h0 = __float2bfloat16(p0);
                __nv_bfloat16 h1 = __float2bfloat16(p1);
                __nv_bfloat16 g0 = __float2bfloat16(p0 - __bfloat162float(h0));
                __nv_bfloat16 g1 = __float2bfloat16(p1 - __bfloat162float(h1));
                hp[j] = (uint32_t)__bfloat16_as_ushort(h0) |
                        ((uint32_t)__bfloat16_as_ushort(h1) << 16);
                lp[j] = (uint32_t)__bfloat16_as_ushort(g0) |
                        ((uint32_t)__bfloat16_as_ushort(g1) << 16);
            }
            l_part += lsum;
#pragma unroll
            for (int qb = 0; qb < 4; qb++) {
                uint32_t off = srow * 128 + ch * 64 + qb * 16;
                uint32_t swo = off ^ ((off >> 3) & 0x70);
                *reinterpret_cast<uint4*>(tgen + A_PHI + chalf * 16384 + swo) =
                    make_uint4(hp[4 * qb], hp[4 * qb + 1], hp[4 * qb + 2], hp[4 * qb + 3]);
                *reinterpret_cast<uint4*>(tgen + A_PLO + chalf * 16384 + swo) =
                    make_uint4(lp[4 * qb], lp[4 * qb + 1], lp[4 * qb + 2], lp[4 * qb + 3]);
            }
        }
        CP_WAIT0();
        FENCE_ASYNC();
        __syncthreads();

        if (wid == 0 && elect_one()) {
            if (it + 1 < NIT) {
                const uint32_t tm_Sn = ((it + 1) & 1) ? tm_S1 : tm_S0;
                uint64_t da[3] = { dQhi, dQhi, dQlo };
                uint64_t db[3] = { dKh, dKl, dKh };
#pragma unroll
                for (int t = 0; t < 3; t++)
#pragma unroll
                    for (int ks = 0; ks < 4; ks++)
                        mma_bf16_ss(tm_Sn, da[t] + ks * 2, db[t] + ks * 2, GEMM_IDESC,
                                    (t | ks) ? 1u : 0u);
                TCGEN05_COMMIT(SBAR);
            }
            const int vb = it & 1;
#pragma unroll
            for (int hf = 0; hf < 2; hf++) {
                uint64_t dPhi = make_desc_sw128(tbase + A_PHI + hf * 16384);
                uint64_t dPlo = make_desc_sw128(tbase + A_PLO + hf * 16384);
                uint64_t dVhi = make_desc_sw128(tbase + A_V(vb) + hf * 8192);
                uint64_t dVlo = make_desc_sw128(tbase + A_V(vb) + 16384 + hf * 8192);
                uint64_t da2[3] = { dPhi, dPhi, dPlo };
                uint64_t db2[3] = { dVhi, dVlo, dVhi };
#pragma unroll
                for (int t = 0; t < 3; t++)
#pragma unroll
                    for (int ks = 0; ks < 4; ks++)
                        mma_bf16_ss(tm_O, da2[t] + ks * 2, db2[t] + ks * 2, PV_IDESC,
                                    (it | hf | t | ks) ? 1u : 0u);
            }
            TCGEN05_COMMIT(PVBAR);
        }
    }

    MBARRIER_WAIT_PARITY(PVBAR, ph_pv);
    TCGEN05_FENCE_AFTER();

    lpart[chalf * 128 + srow] = l_part;
    __syncthreads();
    if (wid < 4) {
        const int r = wid * 32 + lid;
        float inv = 1.f / (lpart[r] + lpart[128 + r]);
        uint32_t o0[32], o1[32];
        TCGEN05_LD_X32(o0, tm_O);
        TCGEN05_LD_X32(o1, tm_O + 32);
        TCGEN05_WAIT_LD();
        TCGEN05_FENCE_BEFORE();
        uint4* hdst = reinterpret_cast<uint4*>(Ohi + (size_t)(q0 + r) * NQD + h * HD);
        uint4* ldst = reinterpret_cast<uint4*>(Olo + (size_t)(q0 + r) * NQD + h * HD);
#pragma unroll
        for (int j = 0; j < 8; j++) {
            uint32_t hw[4], lw[4];
#pragma unroll
            for (int w = 0; w < 4; w++) {
                const int i = 8 * j + 2 * w;
                float v0 = __uint_as_float(i < 32 ? o0[i] : o1[i - 32]) * inv;
                float v1 = __uint_as_float((i + 1) < 32 ? o0[i + 1] : o1[i + 1 - 32]) * inv;
                __nv_bfloat16 h0 = __float2bfloat16(v0);
                __nv_bfloat16 h1 = __float2bfloat16(v1);
                __nv_bfloat16 l0 = __float2bfloat16(v0 - __bfloat162float(h0));
                __nv_bfloat16 l1 = __float2bfloat16(v1 - __bfloat162float(h1));
                hw[w] = (uint32_t)__bfloat16_as_ushort(h0) |
                        ((uint32_t)__bfloat16_as_ushort(h1) << 16);
                lw[w] = (uint32_t)__bfloat16_as_ushort(l0) |
                        ((uint32_t)__bfloat16_as_ushort(l1) << 16);
            }
            hdst[j] = make_uint4(hw[0], hw[1], hw[2], hw[3]);
            ldst[j] = make_uint4(lw[0], lw[1], lw[2], lw[3]);
        }
    }
    __syncthreads();
    if (wid == 0) { TCGEN05_RELINQ(); TCGEN05_DEALLOC(tmem, 512); }

#else  // slow correct fallback (plain pass; never selected)
    const int tid = threadIdx.x;
    if (tid >= 128) return;
    const int h  = blockIdx.y;
    const int hk = h >> 2;
    const int t  = blockIdx.x * 128 + tid;
    float qv[64], o[64];
#pragma unroll
    for (int d = 0; d < 64; d++) {
        size_t qi = (size_t)t * NQD + h * HD + d;
        qv[d] = __bfloat162float(Qhi[qi]) + __bfloat162float(Qlo[qi]);
        o[d] = 0.f;
    }
    float l = 0.f;
    for (int c = 0; c < S_LEN; c++) {
        float s = 0.f;
        size_t kbase = (size_t)c * NKVD + hk * HD;
        for (int d = 0; d < 64; d++)
            s += qv[d] * (__bfloat162float(Khi[kbase + d]) + __bfloat162float(Klo[kbase + d]));
        float p = expf(s);
        l += p;
        for (int d = 0; d < 64; d++) {
            size_t vi = ((size_t)hk * HD + d) * S_LEN + c;
            o[d] += p * (__bfloat162float(Vthi[vi]) + __bfloat162float(Vtlo[vi]));
        }
    }
    float inv = 1.f / l;
    for (int d = 0; d < 64; d++) {
        float v0 = o[d] * inv;
        __nv_bfloat16 h0 = __float2bfloat16(v0);
        Ohi[(size_t)t * NQD + h * HD + d] = h0;
        Olo[(size_t)t * NQD + h * HD + d] = __float2bfloat16(v0 - __bfloat162float(h0));
    }
#endif
}

// ---------------------------------------------------------------------------
// Launch.
// ---------------------------------------------------------------------------
extern "C" void kernel_launch(void* const* d_in, const int* in_sizes, int n_in,
                              void* d_out, int out_size)
{
    const float* X  = (const float*)d_in[0];
    const float* Wq = (const float*)d_in[1];
    const float* Wk = (const float*)d_in[2];
    const float* Wv = (const float*)d_in[3];
    const float* Wo = (const float*)d_in[4];
    float* out = (float*)d_out;

    float *v;
    cudaGetSymbolAddress((void**)&v, g_v);

    __nv_bfloat16 *xhi, *xlo, *chi, *clo;
    __nv_bfloat16 *wqh, *wql, *wkh, *wkl, *wvh, *wvl, *woh, *wol;
    __nv_bfloat16 *qsh, *qsl, *ksh, *ksl, *vth, *vtl;
    cudaGetSymbolAddress((void**)&xhi, g_xhi); cudaGetSymbolAddress((void**)&xlo, g_xlo);
    cudaGetSymbolAddress((void**)&chi, g_chi); cudaGetSymbolAddress((void**)&clo, g_clo);
    cudaGetSymbolAddress((void**)&wqh, g_wqhi); cudaGetSymbolAddress((void**)&wql, g_wqlo);
    cudaGetSymbolAddress((void**)&wkh, g_wkhi); cudaGetSymbolAddress((void**)&wkl, g_wklo);
    cudaGetSymbolAddress((void**)&wvh, g_wvhi); cudaGetSymbolAddress((void**)&wvl, g_wvlo);
    cudaGetSymbolAddress((void**)&woh, g_wohi); cudaGetSymbolAddress((void**)&wol, g_wolo);
    cudaGetSymbolAddress((void**)&qsh, g_qshi); cudaGetSymbolAddress((void**)&qsl, g_qslo);
    cudaGetSymbolAddress((void**)&ksh, g_kshi); cudaGetSymbolAddress((void**)&ksl, g_kslo);
    cudaGetSymbolAddress((void**)&vth, g_vthi); cudaGetSymbolAddress((void**)&vtl, g_vtlo);

    cudaFuncSetAttribute(tc_gemm_kernel,     cudaFuncAttributeMaxDynamicSharedMemorySize, GEMM_SMEM);
    cudaFuncSetAttribute(tc_gemm_qkv_kernel, cudaFuncAttributeMaxDynamicSharedMemorySize, GEMM_SMEM);
    cudaFuncSetAttribute(attn_tc_kernel,     cudaFuncAttributeMaxDynamicSharedMemorySize, ATT_SMEM);

    // 0-4: tables + operand conversions
    rope_table_kernel<<<(S_LEN * 32 + 255) / 256, 256>>>();
    convert_split_kernel<<<(S_LEN * HIDDEN / 4 + 255) / 256, 256>>>(
        (const float4*)X, (uint2*)xhi, (uint2*)xlo, S_LEN * HIDDEN / 4);
    convert_wT_kernel<<<dim3(NQD  / 32, HIDDEN / 32), dim3(32, 8)>>>(Wq, wqh, wql, HIDDEN, NQD);
    convert_wT_kernel<<<dim3(NKVD / 32, HIDDEN / 32), dim3(32, 8)>>>(Wk, wkh, wkl, HIDDEN, NKVD);
    convert_wT_kernel<<<dim3(NKVD / 32, HIDDEN / 32), dim3(32, 8)>>>(Wv, wvh, wvl, HIDDEN, NKVD);

    // 5: fused QKV projections (rope+split epilogues for Q/K; fp32 V)
    tc_gemm_qkv_kernel<<<dim3(24, S_LEN / 128), 256, GEMM_SMEM>>>(
        xhi, xlo, wqh, wql, wkh, wkl, wvh, wvl, qsh, qsl, ksh, ksl, v);

    // 6-7: V transpose prep + Wo conversion
    prep_vt_kernel<<<dim3(NKVD / 32, S_LEN / 32), dim3(32, 8)>>>(v, vth, vtl);
    convert_wT_kernel<<<dim3(HIDDEN / 32, NQD / 32), dim3(32, 8)>>>(Wo, woh, wol, NQD, HIDDEN);

    // 8: attention
    attn_tc_kernel<<<dim3(S_LEN / 128, NH), 256, ATT_SMEM>>>(
        qsh, qsl, ksh, ksl, vth, vtl, chi, clo);

    // 9: output projection
    tc_gemm_kernel<<<dim3(HIDDEN / 128, S_LEN / 128), 256, GEMM_SMEM>>>(
        chi, clo, woh, wol, out, S_LEN, HIDDEN, NQD);
}

// round 17
// speedup vs baseline: 1.0617x; 1.0617x over previous
#include <cuda_runtime.h>
#include <cuda_bf16.h>
#include <cstdint>
#include <math.h>

// ---------------------------------------------------------------------------
// Arch-feature gate: tcgen05 arch-specific instrs only exist on sm_10Xa.
// The harness also compiles a plain compute_103 pass -> fallback bodies there.
// ---------------------------------------------------------------------------
#if defined(__CUDA_ARCH__)
#  if defined(__CUDA_ARCH_FEAT_SM103_ALL) || defined(__CUDA_ARCH_FEAT_SM100_ALL) || \
      defined(__CUDA_ARCH_FEAT_SM101_ALL)
#    define HAS_TCGEN05 1
#  elif defined(__CUDA_ARCH_HAS_FEATURE__)
#    if __CUDA_ARCH_HAS_FEATURE__(SM103_ALL) || __CUDA_ARCH_HAS_FEATURE__(SM100_ALL)
#      define HAS_TCGEN05 1
#    else
#      define HAS_TCGEN05 0
#    endif
#  else
#    define HAS_TCGEN05 0
#  endif
#else
#  define HAS_TCGEN05 0
#endif

// ---------------------------------------------------------------------------
// Problem constants
// ---------------------------------------------------------------------------
#define HIDDEN 2048
#define S_LEN  2048
#define NH     32
#define NKV    8
#define HD     64
#define NQD    (NH * HD)    // 2048
#define NKVD   (NKV * HD)   // 512

// ---------------------------------------------------------------------------
// Device-global scratch
// ---------------------------------------------------------------------------
__device__ float g_q  [S_LEN * NQD];
__device__ float g_k  [S_LEN * NKVD];
__device__ float g_v  [S_LEN * NKVD];
__device__ float g_cos[S_LEN * 32];
__device__ float g_sin[S_LEN * 32];

__device__ __nv_bfloat16 g_xhi[S_LEN * HIDDEN], g_xlo[S_LEN * HIDDEN];
__device__ __nv_bfloat16 g_chi[S_LEN * NQD],    g_clo[S_LEN * NQD];
__device__ __nv_bfloat16 g_wqhi[NQD  * HIDDEN], g_wqlo[NQD  * HIDDEN]; // [N][K]
__device__ __nv_bfloat16 g_wkhi[NKVD * HIDDEN], g_wklo[NKVD * HIDDEN];
__device__ __nv_bfloat16 g_wvhi[NKVD * HIDDEN], g_wvlo[NKVD * HIDDEN];
__device__ __nv_bfloat16 g_wohi[HIDDEN * NQD],  g_wolo[HIDDEN * NQD];  // [N][K]

// attention operands (rotated; Q pre-scaled by 1/8)
__device__ __nv_bfloat16 g_qshi[S_LEN * NQD],  g_qslo[S_LEN * NQD];
__device__ __nv_bfloat16 g_kshi[S_LEN * NKVD], g_kslo[S_LEN * NKVD];
__device__ __nv_bfloat16 g_vthi[NKVD * S_LEN], g_vtlo[NKVD * S_LEN];  // [hk*64+d][t]

// ---------------------------------------------------------------------------
// PTX helpers (sm_10Xa pass only)
// ---------------------------------------------------------------------------
#if HAS_TCGEN05

__device__ __forceinline__ uint32_t smem_u32(const void* p) {
    uint32_t a;
    asm("{ .reg .u64 t; cvta.to.shared.u64 t, %1; cvt.u32.u64 %0, t; }"
        : "=r"(a) : "l"(p));
    return a;
}

__device__ __forceinline__ uint32_t elect_one() {
    uint32_t pred;
    asm volatile("{ .reg .pred p; elect.sync _|p, 0xFFFFFFFF; selp.b32 %0, 1, 0, p; }"
                 : "=r"(pred));
    return pred;
}

#define MBARRIER_INIT(addr, cnt) \
    asm volatile("mbarrier.init.shared.b64 [%0], %1;" :: "r"(addr), "r"(cnt) : "memory")

#define MBARRIER_WAIT_PARITY(mbar, par) do {                                          \
    uint32_t _m = (mbar); uint32_t _p = (par); uint32_t _done;                        \
    asm volatile("{ .reg .pred p; mbarrier.try_wait.parity.acquire.cta.shared::cta.b64 p, [%1], %2;" \
                 " selp.b32 %0, 1, 0, p; }" : "=r"(_done) : "r"(_m), "r"(_p) : "memory"); \
    if (!_done) {                                                                     \
        asm volatile("{ .reg .pred P1; WAIT_LOOP_%=:"                                 \
            " mbarrier.try_wait.parity.acquire.cta.shared::cta.b64 P1, [%0], %1, 0x989680;" \
            " @P1 bra.uni WAIT_DONE_%=; bra.uni WAIT_LOOP_%=; WAIT_DONE_%=: }"        \
            :: "r"(_m), "r"(_p) : "memory");                                          \
    }                                                                                 \
} while (0)

#define TCGEN05_ALLOC(sm_addr, ncols) \
    asm volatile("tcgen05.alloc.cta_group::1.sync.aligned.shared::cta.b32 [%0], %1;" \
                 :: "r"(sm_addr), "r"(ncols) : "memory")
#define TCGEN05_DEALLOC(tm, ncols) \
    asm volatile("tcgen05.dealloc.cta_group::1.sync.aligned.b32 %0, %1;" :: "r"(tm), "r"(ncols))
#define TCGEN05_RELINQ() \
    asm volatile("tcgen05.relinquish_alloc_permit.cta_group::1.sync.aligned;")
#define TCGEN05_COMMIT(mbar) \
    asm volatile("tcgen05.commit.cta_group::1.mbarrier::arrive::one.shared::cluster.b64 [%0];" \
                 :: "r"(mbar) : "memory")
#define TCGEN05_WAIT_LD() asm volatile("tcgen05.wait::ld.sync.aligned;" ::: "memory")
#define TCGEN05_FENCE_AFTER()  asm volatile("tcgen05.fence::after_thread_sync;" ::: "memory")
#define TCGEN05_FENCE_BEFORE() asm volatile("tcgen05.fence::before_thread_sync;" ::: "memory")
#define FENCE_ASYNC() asm volatile("fence.proxy.async.shared::cta;" ::: "memory")

#define CP_COMMIT() asm volatile("cp.async.commit_group;" ::: "memory")
#define CP_WAIT1()  asm volatile("cp.async.wait_group 1;" ::: "memory")
#define CP_WAIT0()  asm volatile("cp.async.wait_group 0;" ::: "memory")

#define TCGEN05_LD_X32(r, tm) \
    asm volatile( \
        "tcgen05.ld.sync.aligned.32x32b.x32.b32 " \
        "{%0, %1, %2, %3, %4, %5, %6, %7, %8, %9, %10, %11, %12, %13, %14, %15, " \
        " %16, %17, %18, %19, %20, %21, %22, %23, %24, %25, %26, %27, %28, %29, %30, %31}, [%32];" \
        : "=r"((r)[0]),  "=r"((r)[1]),  "=r"((r)[2]),  "=r"((r)[3]), \
          "=r"((r)[4]),  "=r"((r)[5]),  "=r"((r)[6]),  "=r"((r)[7]), \
          "=r"((r)[8]),  "=r"((r)[9]),  "=r"((r)[10]), "=r"((r)[11]), \
          "=r"((r)[12]), "=r"((r)[13]), "=r"((r)[14]), "=r"((r)[15]), \
          "=r"((r)[16]), "=r"((r)[17]), "=r"((r)[18]), "=r"((r)[19]), \
          "=r"((r)[20]), "=r"((r)[21]), "=r"((r)[22]), "=r"((r)[23]), \
          "=r"((r)[24]), "=r"((r)[25]), "=r"((r)[26]), "=r"((r)[27]), \
          "=r"((r)[28]), "=r"((r)[29]), "=r"((r)[30]), "=r"((r)[31]) \
        : "r"(tm))

__device__ __forceinline__ uint64_t make_desc_sw128(uint32_t addr) {
    return (uint64_t(2) << 61) | (uint64_t(1) << 46) | (uint64_t(64) << 32) |
           (uint64_t(1) << 16) | ((uint64_t)(addr >> 4) & 0x3FFF);
}

__device__ __forceinline__ void mma_bf16_ss(uint32_t d_tmem, uint64_t a_desc,
                                            uint64_t b_desc, uint32_t idesc, uint32_t en) {
    asm volatile(
        "{\n\t.reg .pred p;\n\t"
        "setp.ne.u32 p, %5, 0;\n\t"
        "tcgen05.mma.cta_group::1.kind::f16 [%0], %1, %2, %3, {%4, %4, %4, %4}, p;\n\t"
        "}"
        :: "r"(d_tmem), "l"(a_desc), "l"(b_desc), "r"(idesc), "r"(0u), "r"(en)
        : "memory");
}

#define GEMM_IDESC ((1u << 4) | (1u << 7) | (1u << 10) | ((128u / 8u) << 17) | ((128u / 16u) << 24))
#define PV_IDESC   ((1u << 4) | (1u << 7) | (1u << 10) | ((64u  / 8u) << 17) | ((128u / 16u) << 24))

#endif  // HAS_TCGEN05

// ---------------------------------------------------------------------------
// Conversion / prep kernels
// ---------------------------------------------------------------------------
__global__ void convert_split_kernel(const float4* __restrict__ in,
                                     uint2* __restrict__ hi,
                                     uint2* __restrict__ lo, int n4)
{
    int i = blockIdx.x * blockDim.x + threadIdx.x;
    if (i >= n4) return;
    float4 x = in[i];
    __nv_bfloat16 h0 = __float2bfloat16(x.x), h1 = __float2bfloat16(x.y);
    __nv_bfloat16 h2 = __float2bfloat16(x.z), h3 = __float2bfloat16(x.w);
    __nv_bfloat16 l0 = __float2bfloat16(x.x - __bfloat162float(h0));
    __nv_bfloat16 l1 = __float2bfloat16(x.y - __bfloat162float(h1));
    __nv_bfloat16 l2 = __float2bfloat16(x.z - __bfloat162float(h2));
    __nv_bfloat16 l3 = __float2bfloat16(x.w - __bfloat162float(h3));
    uint2 ho, loo;
    ho.x  = (uint32_t)__bfloat16_as_ushort(h0) | ((uint32_t)__bfloat16_as_ushort(h1) << 16);
    ho.y  = (uint32_t)__bfloat16_as_ushort(h2) | ((uint32_t)__bfloat16_as_ushort(h3) << 16);
    loo.x = (uint32_t)__bfloat16_as_ushort(l0) | ((uint32_t)__bfloat16_as_ushort(l1) << 16);
    loo.y = (uint32_t)__bfloat16_as_ushort(l2) | ((uint32_t)__bfloat16_as_ushort(l3) << 16);
    hi[i] = ho;
    lo[i] = loo;
}

__global__ void convert_wT_kernel(const float* __restrict__ W,
                                  __nv_bfloat16* __restrict__ hi,
                                  __nv_bfloat16* __restrict__ lo, int K, int N)
{
    __shared__ float t[32][33];
    int n0 = blockIdx.x * 32, k0 = blockIdx.y * 32;
    int tx = threadIdx.x, ty = threadIdx.y;  // block (32, 8)
#pragma unroll
    for (int i = ty; i < 32; i += 8)
        t[i][tx] = W[(size_t)(k0 + i) * N + n0 + tx];
    __syncthreads();
#pragma unroll
    for (int i = ty; i < 32; i += 8) {
        float x = t[tx][i];
        __nv_bfloat16 h = __float2bfloat16(x);
        size_t o = (size_t)(n0 + i) * K + k0 + tx;
        hi[o] = h;
        lo[o] = __float2bfloat16(x - __bfloat162float(h));
    }
}

// RoPE tables. sincosf is (x, &sin, &cos) — SIN FIRST.
__global__ void rope_table_kernel()
{
    int idx = blockIdx.x * blockDim.x + threadIdx.x;
    if (idx >= S_LEN * 32) return;
    int p = idx & 31;
    int t = idx >> 5;
    float inv_freq = (float)exp(-((double)(2 * p) / 64.0) * log(10000.0));
    float ang = (float)t * inv_freq;
    float s, c;
    sincosf(ang, &s, &c);
    g_cos[idx] = c;
    g_sin[idx] = s;
}

// Vectorized rope+scale+split: 8 floats (4 pairs) per thread (R15-proven).
__global__ void prep_rope_split_kernel(const float4* __restrict__ src,
                                       uint4* __restrict__ hi,
                                       uint4* __restrict__ lo,
                                       int W, float scale, int n8)
{
    int idx = blockIdx.x * blockDim.x + threadIdx.x;
    if (idx >= n8) return;
    int wpg = W >> 3;                 // groups per row
    int t   = idx / wpg;
    int g   = (idx % wpg) * 8;        // element col
    int p0  = (g & 63) >> 1;          // 4-aligned pair index
    float4 cs = *reinterpret_cast<const float4*>(g_cos + t * 32 + p0);
    float4 sn = *reinterpret_cast<const float4*>(g_sin + t * 32 + p0);
    float4 a = src[idx * 2];
    float4 b = src[idx * 2 + 1];
    float e0 = (a.x * cs.x - a.y * sn.x) * scale, o0 = (a.x * sn.x + a.y * cs.x) * scale;
    float e1 = (a.z * cs.y - a.w * sn.y) * scale, o1 = (a.z * sn.y + a.w * cs.y) * scale;
    float e2 = (b.x * cs.z - b.y * sn.z) * scale, o2 = (b.x * sn.z + b.y * cs.z) * scale;
    float e3 = (b.z * cs.w - b.w * sn.w) * scale, o3 = (b.z * sn.w + b.w * cs.w) * scale;
    float v[8] = { e0, o0, e1, o1, e2, o2, e3, o3 };
    uint32_t hw[4], lw[4];
#pragma unroll
    for (int j = 0; j < 4; j++) {
        __nv_bfloat16 ha = __float2bfloat16(v[2 * j]);
        __nv_bfloat16 hb = __float2bfloat16(v[2 * j + 1]);
        __nv_bfloat16 la = __float2bfloat16(v[2 * j]     - __bfloat162float(ha));
        __nv_bfloat16 lb = __float2bfloat16(v[2 * j + 1] - __bfloat162float(hb));
        hw[j] = (uint32_t)__bfloat16_as_ushort(ha) | ((uint32_t)__bfloat16_as_ushort(hb) << 16);
        lw[j] = (uint32_t)__bfloat16_as_ushort(la) | ((uint32_t)__bfloat16_as_ushort(lb) << 16);
    }
    hi[idx] = make_uint4(hw[0], hw[1], hw[2], hw[3]);
    lo[idx] = make_uint4(lw[0], lw[1], lw[2], lw[3]);
}

__global__ void prep_vt_kernel(const float* __restrict__ V,
                               __nv_bfloat16* __restrict__ hi,
                               __nv_bfloat16* __restrict__ lo)
{
    __shared__ float tile[32][33];
    int c0 = blockIdx.x * 32;
    int t0 = blockIdx.y * 32;
    int tx = threadIdx.x, ty = threadIdx.y;  // (32, 8)
#pragma unroll
    for (int i = ty; i < 32; i += 8)
        tile[i][tx] = V[(size_t)(t0 + i) * NKVD + c0 + tx];
    __syncthreads();
#pragma unroll
    for (int i = ty; i < 32; i += 8) {
        float x = tile[tx][i];
        __nv_bfloat16 h = __float2bfloat16(x);
        size_t o = (size_t)(c0 + i) * S_LEN + t0 + tx;
        hi[o] = h;
        lo[o] = __float2bfloat16(x - __bfloat162float(h));
    }
}

// ---------------------------------------------------------------------------
// tcgen05 split-bf16 GEMM mainloop (R12-proven): cp.async 3-stage pipeline,
// 2 MMA chunks in flight.
// ---------------------------------------------------------------------------
#define GK 64
#define TILE_B (128 * GK * 2)
#define STAGE_B (4 * TILE_B)
#define GEMM_SMEM (2048 + 3 * STAGE_B)   // 198656 B

#if HAS_TCGEN05
__device__ __forceinline__ void load_tile_cpasync(uint32_t sdst,
                                                  const __nv_bfloat16* __restrict__ g,
                                                  int row0, int ld, int k0, int tid)
{
    const char* gb = (const char*)(g + (size_t)row0 * ld + k0);
#pragma unroll
    for (int i = 0; i < 4; i++) {
        int v  = i * 256 + tid;          // 0..1023 vectors of 16B
        int r  = v >> 3;                 // row 0..127
        int vc = (v & 7) << 4;           // byte col 0..112
        uint32_t off = r * 128 + vc;
        uint32_t swo = off ^ ((off >> 3) & 0x70);
        asm volatile("cp.async.cg.shared.global [%0], [%1], 16;"
                     :: "r"(sdst + swo), "l"(gb + (size_t)r * (ld * 2) + vc));
    }
}

__device__ __forceinline__ void gemm_mainloop(
    uint32_t sb, uint32_t tbase, uint32_t tmem,
    const __nv_bfloat16* __restrict__ Ahi, const __nv_bfloat16* __restrict__ Alo,
    const __nv_bfloat16* __restrict__ Bhi, const __nv_bfloat16* __restrict__ Blo,
    int m0, int n0, int K, int tid, int wid)
{
    const uint32_t BAR0 = sb, BAR1 = sb + 8;
    const int nchunks = K / GK;

    {
        uint32_t sa = tbase;
        load_tile_cpasync(sa + 0 * TILE_B, Ahi, m0, K, 0, tid);
        load_tile_cpasync(sa + 1 * TILE_B, Alo, m0, K, 0, tid);
        load_tile_cpasync(sa + 2 * TILE_B, Bhi, n0, K, 0, tid);
        load_tile_cpasync(sa + 3 * TILE_B, Blo, n0, K, 0, tid);
        CP_COMMIT();
    }
    if (nchunks > 1) {
        uint32_t sa = tbase + STAGE_B;
        load_tile_cpasync(sa + 0 * TILE_B, Ahi, m0, K, GK, tid);
        load_tile_cpasync(sa + 1 * TILE_B, Alo, m0, K, GK, tid);
        load_tile_cpasync(sa + 2 * TILE_B, Bhi, n0, K, GK, tid);
        load_tile_cpasync(sa + 3 * TILE_B, Blo, n0, K, GK, tid);
    }
    CP_COMMIT();

    int ph0 = 0, ph1 = 0;
    for (int c = 0; c < nchunks; c++) {
        CP_WAIT1();
        FENCE_ASYNC();
        __syncthreads();

        if (wid == 0 && elect_one()) {
            const uint32_t sa = tbase + (uint32_t)(c % 3) * STAGE_B;
            uint64_t dAhi = make_desc_sw128(sa + 0 * TILE_B);
            uint64_t dAlo = make_desc_sw128(sa + 1 * TILE_B);
            uint64_t dBhi = make_desc_sw128(sa + 2 * TILE_B);
            uint64_t dBlo = make_desc_sw128(sa + 3 * TILE_B);
            uint64_t da[3] = { dAhi, dAhi, dAlo };
            uint64_t db[3] = { dBhi, dBlo, dBhi };
#pragma unroll
            for (int t = 0; t < 3; t++)
#pragma unroll
                for (int ks = 0; ks < 4; ks++)
                    mma_bf16_ss(tmem, da[t] + ks * 2, db[t] + ks * 2, GEMM_IDESC,
                                (c | t | ks) ? 1u : 0u);
            TCGEN05_COMMIT((c & 1) ? BAR1 : BAR0);
        }

        if (c >= 1) {
            if ((c - 1) & 1) { MBARRIER_WAIT_PARITY(BAR1, ph1); ph1 ^= 1; }
            else             { MBARRIER_WAIT_PARITY(BAR0, ph0); ph0 ^= 1; }
        }

        if (c + 2 < nchunks) {
            uint32_t sa = tbase + (uint32_t)((c + 2) % 3) * STAGE_B;
            const int k2 = (c + 2) * GK;
            load_tile_cpasync(sa + 0 * TILE_B, Ahi, m0, K, k2, tid);
            load_tile_cpasync(sa + 1 * TILE_B, Alo, m0, K, k2, tid);
            load_tile_cpasync(sa + 2 * TILE_B, Bhi, n0, K, k2, tid);
            load_tile_cpasync(sa + 3 * TILE_B, Blo, n0, K, k2, tid);
        }
        CP_COMMIT();
    }

    if ((nchunks - 1) & 1) { MBARRIER_WAIT_PARITY(BAR1, ph1); }
    else                   { MBARRIER_WAIT_PARITY(BAR0, ph0); }
    TCGEN05_FENCE_AFTER();
}
#endif

// Wo projection: fp32 C output.
__global__ __launch_bounds__(256, 1) void tc_gemm_kernel(
    const __nv_bfloat16* __restrict__ Ahi, const __nv_bfloat16* __restrict__ Alo,
    const __nv_bfloat16* __restrict__ Bhi, const __nv_bfloat16* __restrict__ Blo,
    float* __restrict__ C, int M, int N, int K)
{
#if HAS_TCGEN05
    extern __shared__ char smem[];
    const uint32_t sb = smem_u32(smem);
    const int tid = threadIdx.x;
    const int wid = tid >> 5;
    const int lid = tid & 31;
    const int m0 = blockIdx.y * 128;
    const int n0 = blockIdx.x * 128;
    const uint32_t TPTR = sb + 16;
    const uint32_t tbase = (sb + 24 + 1023) & ~1023u;

    if (wid == 0) TCGEN05_ALLOC(TPTR, 128);
    if (tid == 0) { MBARRIER_INIT(sb, 1); MBARRIER_INIT(sb + 8, 1); }
    __syncthreads();
    uint32_t tmem;
    asm volatile("ld.shared.b32 %0, [%1];" : "=r"(tmem) : "r"(TPTR));

    gemm_mainloop(sb, tbase, tmem, Ahi, Alo, Bhi, Blo, m0, n0, K, tid, wid);

    if (wid < 4) {
        const int m = m0 + wid * 32 + lid;
        float* crow = C + (size_t)m * N + n0;
#pragma unroll
        for (int nb = 0; nb < 4; nb++) {
            uint32_t dreg[32];
            TCGEN05_LD_X32(dreg, tmem + nb * 32);
            TCGEN05_WAIT_LD();
            TCGEN05_FENCE_BEFORE();
            float4* dst = reinterpret_cast<float4*>(crow + nb * 32);
#pragma unroll
            for (int j = 0; j < 8; j++)
                dst[j] = make_float4(__uint_as_float(dreg[4 * j + 0]),
                                     __uint_as_float(dreg[4 * j + 1]),
                                     __uint_as_float(dreg[4 * j + 2]),
                                     __uint_as_float(dreg[4 * j + 3]));
        }
    }
    __syncthreads();
    if (wid == 0) { TCGEN05_RELINQ(); TCGEN05_DEALLOC(tmem, 128); }

#else  // FFMA fallback (plain pass; never selected at runtime)
    __shared__ float As[64][33];
    __shared__ float Bs[64][33];
    const int tid = threadIdx.x;
    const int tx  = tid & 15;
    const int ty  = tid >> 4;
    for (int sub = 0; sub < 4; sub++) {
        const int m0 = blockIdx.y * 128 + (sub >> 1) * 64;
        const int n0 = blockIdx.x * 128 + (sub & 1) * 64;
        float acc[4][4] = {};
        for (int k0 = 0; k0 < K; k0 += 32) {
            __syncthreads();
#pragma unroll
            for (int i = 0; i < 8; i++) {
                int e  = tid * 8 + i;
                int r  = e >> 5;
                int kk = e & 31;
                size_t ai = (size_t)(m0 + r) * K + k0 + kk;
                size_t bi = (size_t)(n0 + r) * K + k0 + kk;
                As[r][kk] = __bfloat162float(Ahi[ai]) + __bfloat162float(Alo[ai]);
                Bs[r][kk] = __bfloat162float(Bhi[bi]) + __bfloat162float(Blo[bi]);
            }
            __syncthreads();
#pragma unroll
            for (int k = 0; k < 32; k++) {
                float a[4], b[4];
#pragma unroll
                for (int i = 0; i < 4; i++) a[i] = As[ty * 4 + i][k];
#pragma unroll
                for (int j = 0; j < 4; j++) b[j] = Bs[tx * 4 + j][k];
#pragma unroll
                for (int i = 0; i < 4; i++)
#pragma unroll
                    for (int j = 0; j < 4; j++) acc[i][j] += a[i] * b[j];
            }
        }
        __syncthreads();
#pragma unroll
        for (int i = 0; i < 4; i++) {
            float4 r = make_float4(acc[i][0], acc[i][1], acc[i][2], acc[i][3]);
            *reinterpret_cast<float4*>(C + (size_t)(m0 + ty * 4 + i) * N + n0 + tx * 4) = r;
        }
    }
#endif
}

// Fused Q/K/V projections, ALL fp32 outputs (no in-epilogue RoPE — the R16
// scatter-gather regression). grid = (24, 16): bx 0-15 Wq -> q, 16-19 Wk -> k,
// 20-23 Wv -> v.
__global__ __launch_bounds__(256, 1) void tc_gemm_qkv_kernel(
    const __nv_bfloat16* __restrict__ xhi, const __nv_bfloat16* __restrict__ xlo,
    const __nv_bfloat16* __restrict__ wqh, const __nv_bfloat16* __restrict__ wql,
    const __nv_bfloat16* __restrict__ wkh, const __nv_bfloat16* __restrict__ wkl,
    const __nv_bfloat16* __restrict__ wvh, const __nv_bfloat16* __restrict__ wvl,
    float* __restrict__ qout, float* __restrict__ kout, float* __restrict__ vout)
{
    const int bx = blockIdx.x;
    const __nv_bfloat16 *Bhi, *Blo;
    float* Cout;
    int n0, ldC;
    if (bx < 16)      { Bhi = wqh; Blo = wql; Cout = qout; n0 = bx * 128;        ldC = NQD;  }
    else if (bx < 20) { Bhi = wkh; Blo = wkl; Cout = kout; n0 = (bx - 16) * 128; ldC = NKVD; }
    else              { Bhi = wvh; Blo = wvl; Cout = vout; n0 = (bx - 20) * 128; ldC = NKVD; }

#if HAS_TCGEN05
    extern __shared__ char smem[];
    const uint32_t sb = smem_u32(smem);
    const int tid = threadIdx.x;
    const int wid = tid >> 5;
    const int lid = tid & 31;
    const int m0 = blockIdx.y * 128;
    const uint32_t TPTR = sb + 16;
    const uint32_t tbase = (sb + 24 + 1023) & ~1023u;

    if (wid == 0) TCGEN05_ALLOC(TPTR, 128);
    if (tid == 0) { MBARRIER_INIT(sb, 1); MBARRIER_INIT(sb + 8, 1); }
    __syncthreads();
    uint32_t tmem;
    asm volatile("ld.shared.b32 %0, [%1];" : "=r"(tmem) : "r"(TPTR));

    gemm_mainloop(sb, tbase, tmem, xhi, xlo, Bhi, Blo, m0, n0, HIDDEN, tid, wid);

    if (wid < 4) {
        const int m = m0 + wid * 32 + lid;
        float* crow = Cout + (size_t)m * ldC + n0;
#pragma unroll
        for (int nb = 0; nb < 4; nb++) {
            uint32_t dreg[32];
            TCGEN05_LD_X32(dreg, tmem + nb * 32);
            TCGEN05_WAIT_LD();
            TCGEN05_FENCE_BEFORE();
            float4* dst = reinterpret_cast<float4*>(crow + nb * 32);
#pragma unroll
            for (int j = 0; j < 8; j++)
                dst[j] = make_float4(__uint_as_float(dreg[4 * j + 0]),
                                     __uint_as_float(dreg[4 * j + 1]),
                                     __uint_as_float(dreg[4 * j + 2]),
                                     __uint_as_float(dreg[4 * j + 3]));
        }
    }
    __syncthreads();
    if (wid == 0) { TCGEN05_RELINQ(); TCGEN05_DEALLOC(tmem, 128); }

#else  // FFMA fallback (plain pass; never selected at runtime)
    __shared__ float As[64][33];
    __shared__ float Bs[64][33];
    const int tid = threadIdx.x;
    const int tx  = tid & 15;
    const int ty  = tid >> 4;
    const int K = HIDDEN;
    for (int sub = 0; sub < 4; sub++) {
        const int m0s = blockIdx.y * 128 + (sub >> 1) * 64;
        const int n0s = n0 + (sub & 1) * 64;
        float acc[4][4] = {};
        for (int k0 = 0; k0 < K; k0 += 32) {
            __syncthreads();
#pragma unroll
            for (int i = 0; i < 8; i++) {
                int e  = tid * 8 + i;
                int r  = e >> 5;
                int kk = e & 31;
                size_t ai = (size_t)(m0s + r) * K + k0 + kk;
                size_t bi = (size_t)(n0s + r) * K + k0 + kk;
                As[r][kk] = __bfloat162float(xhi[ai]) + __bfloat162float(xlo[ai]);
                Bs[r][kk] = __bfloat162float(Bhi[bi]) + __bfloat162float(Blo[bi]);
            }
            __syncthreads();
#pragma unroll
            for (int k = 0; k < 32; k++) {
                float a[4], b[4];
#pragma unroll
                for (int i = 0; i < 4; i++) a[i] = As[ty * 4 + i][k];
#pragma unroll
                for (int j = 0; j < 4; j++) b[j] = Bs[tx * 4 + j][k];
#pragma unroll
                for (int i = 0; i < 4; i++)
#pragma unroll
                    for (int j = 0; j < 4; j++) acc[i][j] += a[i] * b[j];
            }
        }
        __syncthreads();
#pragma unroll
        for (int i = 0; i < 4; i++) {
            float4 r = make_float4(acc[i][0], acc[i][1], acc[i][2], acc[i][3]);
            *reinterpret_cast<float4*>(Cout + (size_t)(m0s + ty * 4 + i) * ldC + n0s + tx * 4) = r;
        }
    }
#endif
}

// ---------------------------------------------------------------------------
// tcgen05 flash attention (R15-proven, unchanged).
// ---------------------------------------------------------------------------
#define A_QHI   0
#define A_QLO   16384
#define A_K     32768                   // Khi at +0, Klo at +16384
#define A_V(b)  (65536 + (b) * 32768)   // Vhi halves +0/+8192, Vlo +16384/+24576
#define A_PHI   131072                  // two col-halves 16K each
#define A_PLO   163840
#define A_TILES_BYTES 196608
#define ATT_SMEM (2112 + 1024 + A_TILES_BYTES)

__global__ __launch_bounds__(256, 1) void attn_tc_kernel(
    const __nv_bfloat16* __restrict__ Qhi, const __nv_bfloat16* __restrict__ Qlo,
    const __nv_bfloat16* __restrict__ Khi, const __nv_bfloat16* __restrict__ Klo,
    const __nv_bfloat16* __restrict__ Vthi, const __nv_bfloat16* __restrict__ Vtlo,
    __nv_bfloat16* __restrict__ Ohi, __nv_bfloat16* __restrict__ Olo)
{
#if HAS_TCGEN05
    extern __shared__ char smem[];
    const uint32_t sb = smem_u32(smem);
    const int tid = threadIdx.x;
    const int wid = tid >> 5;
    const int lid = tid & 31;
    const int h   = blockIdx.y;
    const int q0  = blockIdx.x * 128;
    const int hk  = h >> 2;

    const uint32_t SBAR = sb, PVBAR = sb + 8, TPTR = sb + 16;
    float* lpart = reinterpret_cast<float*>(smem + 32);   // [2][128]
    const uint32_t tbase = (sb + 32 + 1024 + 1023) & ~1023u;
    char* tgen = smem + (tbase - sb);

    if (wid == 0) TCGEN05_ALLOC(TPTR, 512);
    if (tid == 0) { MBARRIER_INIT(SBAR, 1); MBARRIER_INIT(PVBAR, 1); }
    __syncthreads();
    uint32_t tmem;
    asm volatile("ld.shared.b32 %0, [%1];" : "=r"(tmem) : "r"(TPTR));
    const uint32_t tm_S0 = tmem;
    const uint32_t tm_S1 = tmem + 128;
    const uint32_t tm_O  = tmem + 256;

    uint64_t dQhi = make_desc_sw128(tbase + A_QHI);
    uint64_t dQlo = make_desc_sw128(tbase + A_QLO);
    uint64_t dKh  = make_desc_sw128(tbase + A_K);
    uint64_t dKl  = make_desc_sw128(tbase + A_K + 16384);

    // ---- prologue: Q, K(0), V(0) (plain stores) ----
    {
        const char* ghi = (const char*)(Qhi + (size_t)q0 * NQD + h * HD);
        const char* glo = (const char*)(Qlo + (size_t)q0 * NQD + h * HD);
#pragma unroll
        for (int i = 0; i < 4; i++) {
            int v = i * 256 + tid;
            int r = v >> 3;
            int vc = (v & 7) << 4;
            uint32_t off = r * 128 + vc;
            uint32_t swo = off ^ ((off >> 3) & 0x70);
            *reinterpret_cast<uint4*>(tgen + A_QHI + swo) =
                *reinterpret_cast<const uint4*>(ghi + (size_t)r * (NQD * 2) + vc);
            *reinterpret_cast<uint4*>(tgen + A_QLO + swo) =
                *reinterpret_cast<const uint4*>(glo + (size_t)r * (NQD * 2) + vc);
        }
    }
    {
        const char* ghi = (const char*)(Khi + (size_t)0 * NKVD + hk * HD);
        const char* glo = (const char*)(Klo + (size_t)0 * NKVD + hk * HD);
#pragma unroll
        for (int i = 0; i < 4; i++) {
            int v = i * 256 + tid;
            int r = v >> 3;
            int vc = (v & 7) << 4;
            uint32_t off = r * 128 + vc;
            uint32_t swo = off ^ ((off >> 3) & 0x70);
            *reinterpret_cast<uint4*>(tgen + A_K + swo) =
                *reinterpret_cast<const uint4*>(ghi + (size_t)r * (NKVD * 2) + vc);
            *reinterpret_cast<uint4*>(tgen + A_K + 16384 + swo) =
                *reinterpret_cast<const uint4*>(glo + (size_t)r * (NKVD * 2) + vc);
        }
    }
    {
        const char* ghi = (const char*)(Vthi + (size_t)hk * HD * S_LEN + 0);
        const char* glo = (const char*)(Vtlo + (size_t)hk * HD * S_LEN + 0);
        char* vdst = tgen + A_V(0);
#pragma unroll
        for (int i = 0; i < 4; i++) {
            int v = i * 256 + tid;
            int hf = v >> 9;
            int w  = v & 511;
            int d  = w >> 3;
            int vc = (w & 7) << 4;
            uint32_t off = d * 128 + vc;
            uint32_t swo = off ^ ((off >> 3) & 0x70);
            size_t gof = (size_t)d * (S_LEN * 2) + hf * 128 + vc;
            *reinterpret_cast<uint4*>(vdst + hf * 8192 + swo) =
                *reinterpret_cast<const uint4*>(ghi + gof);
            *reinterpret_cast<uint4*>(vdst + 16384 + hf * 8192 + swo) =
                *reinterpret_cast<const uint4*>(glo + gof);
        }
    }
    FENCE_ASYNC();
    __syncthreads();

    // QK(0) -> S0, commit SBAR
    if (wid == 0 && elect_one()) {
        uint64_t da[3] = { dQhi, dQhi, dQlo };
        uint64_t db[3] = { dKh, dKl, dKh };
#pragma unroll
        for (int t = 0; t < 3; t++)
#pragma unroll
            for (int ks = 0; ks < 4; ks++)
                mma_bf16_ss(tm_S0, da[t] + ks * 2, db[t] + ks * 2, GEMM_IDESC,
                            (t | ks) ? 1u : 0u);
        TCGEN05_COMMIT(SBAR);
    }

    const int srow  = (wid & 3) * 32 + lid;
    const int chalf = wid >> 2;
    float l_part = 0.f;
    int ph_s = 0, ph_pv = 0;
    const int NIT = S_LEN / 128;

    for (int it = 0; it < NIT; it++) {
        MBARRIER_WAIT_PARITY(SBAR, ph_s); ph_s ^= 1;
        if (it > 0) { MBARRIER_WAIT_PARITY(PVBAR, ph_pv); ph_pv ^= 1; }
        TCGEN05_FENCE_AFTER();

        if (it + 1 < NIT) {
            const int c1 = (it + 1) * 128;
            const int b1 = (it + 1) & 1;
            load_tile_cpasync(tbase + A_K,         Khi, c1, NKVD, hk * HD, tid);
            load_tile_cpasync(tbase + A_K + 16384, Klo, c1, NKVD, hk * HD, tid);
            {
                const char* ghi = (const char*)(Vthi + (size_t)hk * HD * S_LEN + c1);
                const char* glo = (const char*)(Vtlo + (size_t)hk * HD * S_LEN + c1);
                const uint32_t vdst = tbase + A_V(b1);
#pragma unroll
                for (int i = 0; i < 4; i++) {
                    int v = i * 256 + tid;
                    int hf = v >> 9;
                    int w  = v & 511;
                    int d  = w >> 3;
                    int vc = (w & 7) << 4;
                    uint32_t off = d * 128 + vc;
                    uint32_t swo = off ^ ((off >> 3) & 0x70);
                    size_t gof = (size_t)d * (S_LEN * 2) + hf * 128 + vc;
                    asm volatile("cp.async.cg.shared.global [%0], [%1], 16;"
                                 :: "r"(vdst + hf * 8192 + swo), "l"(ghi + gof));
                    asm volatile("cp.async.cg.shared.global [%0], [%1], 16;"
                                 :: "r"(vdst + 16384 + hf * 8192 + swo), "l"(glo + gof));
                }
            }
        }
        CP_COMMIT();

        const uint32_t tm_Sc = (it & 1) ? tm_S1 : tm_S0;
#pragma unroll
        for (int ch = 0; ch < 2; ch++) {
            uint32_t sreg[32];
            TCGEN05_LD_X32(sreg, tm_Sc + chalf * 64 + ch * 32);
            TCGEN05_WAIT_LD();
            uint32_t hp[16], lp[16];
            float lsum = 0.f;
#pragma unroll
            for (int j = 0; j < 16; j++) {
                float p0 = __expf(__uint_as_float(sreg[2 * j]));
                float p1 = __expf(__uint_as_float(sreg[2 * j + 1]));
                lsum += p0 + p1;
                __nv_bfloat16 h0 = __float2bfloat16(p0);
                __nv_bfloat16 h1 = __float2bfloat16(p1);
                __nv_bfloat16 g0 = __float2bfloat16(p0 - __bfloat162float(h0));
                __nv_bfloat16 g1 = __float2bfloat16(p1 - __bfloat162float(h1));
                hp[j] = (uint32_t)__bfloat16_as_ushort(h0) |
                        ((uint32_t)__bfloat16_as_ushort(h1) << 16);
                lp[j] = (uint32_t)__bfloat16_as_ushort(g0) |
                        ((uint32_t)__bfloat16_as_ushort(g1) << 16);
            }
            l_part += lsum;
#pragma unroll
            for (int qb = 0; qb < 4; qb++) {
                uint32_t off = srow * 128 + ch * 64 + qb * 16;
                uint32_t swo = off ^ ((off >> 3) & 0x70);
                *reinterpret_cast<uint4*>(tgen + A_PHI + chalf * 16384 + swo) =
                    make_uint4(hp[4 * qb], hp[4 * qb + 1], hp[4 * qb + 2], hp[4 * qb + 3]);
                *reinterpret_cast<uint4*>(tgen + A_PLO + chalf * 16384 + swo) =
                    make_uint4(lp[4 * qb], lp[4 * qb + 1], lp[4 * qb + 2], lp[4 * qb + 3]);
            }
        }
        CP_WAIT0();
        FENCE_ASYNC();
        __syncthreads();

        if (wid == 0 && elect_one()) {
            if (it + 1 < NIT) {
                const uint32_t tm_Sn = ((it + 1) & 1) ? tm_S1 : tm_S0;
                uint64_t da[3] = { dQhi, dQhi, dQlo };
                uint64_t db[3] = { dKh, dKl, dKh };
#pragma unroll
                for (int t = 0; t < 3; t++)
#pragma unroll
                    for (int ks = 0; ks < 4; ks++)
                        mma_bf16_ss(tm_Sn, da[t] + ks * 2, db[t] + ks * 2, GEMM_IDESC,
                                    (t | ks) ? 1u : 0u);
                TCGEN05_COMMIT(SBAR);
            }
            const int vb = it & 1;
#pragma unroll
            for (int hf = 0; hf < 2; hf++) {
                uint64_t dPhi = make_desc_sw128(tbase + A_PHI + hf * 16384);
                uint64_t dPlo = make_desc_sw128(tbase + A_PLO + hf * 16384);
                uint64_t dVhi = make_desc_sw128(tbase + A_V(vb) + hf * 8192);
                uint64_t dVlo = make_desc_sw128(tbase + A_V(vb) + 16384 + hf * 8192);
                uint64_t da2[3] = { dPhi, dPhi, dPlo };
                uint64_t db2[3] = { dVhi, dVlo, dVhi };
#pragma unroll
                for (int t = 0; t < 3; t++)
#pragma unroll
                    for (int ks = 0; ks < 4; ks++)
                        mma_bf16_ss(tm_O, da2[t] + ks * 2, db2[t] + ks * 2, PV_IDESC,
                                    (it | hf | t | ks) ? 1u : 0u);
            }
            TCGEN05_COMMIT(PVBAR);
        }
    }

    MBARRIER_WAIT_PARITY(PVBAR, ph_pv);
    TCGEN05_FENCE_AFTER();

    lpart[chalf * 128 + srow] = l_part;
    __syncthreads();
    if (wid < 4) {
        const int r = wid * 32 + lid;
        float inv = 1.f / (lpart[r] + lpart[128 + r]);
        uint32_t o0[32], o1[32];
        TCGEN05_LD_X32(o0, tm_O);
        TCGEN05_LD_X32(o1, tm_O + 32);
        TCGEN05_WAIT_LD();
        TCGEN05_FENCE_BEFORE();
        uint4* hdst = reinterpret_cast<uint4*>(Ohi + (size_t)(q0 + r) * NQD + h * HD);
        uint4* ldst = reinterpret_cast<uint4*>(Olo + (size_t)(q0 + r) * NQD + h * HD);
#pragma unroll
        for (int j = 0; j < 8; j++) {
            uint32_t hw[4], lw[4];
#pragma unroll
            for (int w = 0; w < 4; w++) {
                const int i = 8 * j + 2 * w;
                float v0 = __uint_as_float(i < 32 ? o0[i] : o1[i - 32]) * inv;
                float v1 = __uint_as_float((i + 1) < 32 ? o0[i + 1] : o1[i + 1 - 32]) * inv;
                __nv_bfloat16 h0 = __float2bfloat16(v0);
                __nv_bfloat16 h1 = __float2bfloat16(v1);
                __nv_bfloat16 l0 = __float2bfloat16(v0 - __bfloat162float(h0));
                __nv_bfloat16 l1 = __float2bfloat16(v1 - __bfloat162float(h1));
                hw[w] = (uint32_t)__bfloat16_as_ushort(h0) |
                        ((uint32_t)__bfloat16_as_ushort(h1) << 16);
                lw[w] = (uint32_t)__bfloat16_as_ushort(l0) |
                        ((uint32_t)__bfloat16_as_ushort(l1) << 16);
            }
            hdst[j] = make_uint4(hw[0], hw[1], hw[2], hw[3]);
            ldst[j] = make_uint4(lw[0], lw[1], lw[2], lw[3]);
        }
    }
    __syncthreads();
    if (wid == 0) { TCGEN05_RELINQ(); TCGEN05_DEALLOC(tmem, 512); }

#else  // slow correct fallback (plain pass; never selected)
    const int tid = threadIdx.x;
    if (tid >= 128) return;
    const int h  = blockIdx.y;
    const int hk = h >> 2;
    const int t  = blockIdx.x * 128 + tid;
    float qv[64], o[64];
#pragma unroll
    for (int d = 0; d < 64; d++) {
        size_t qi = (size_t)t * NQD + h * HD + d;
        qv[d] = __bfloat162float(Qhi[qi]) + __bfloat162float(Qlo[qi]);
        o[d] = 0.f;
    }
    float l = 0.f;
    for (int c = 0; c < S_LEN; c++) {
        float s = 0.f;
        size_t kbase = (size_t)c * NKVD + hk * HD;
        for (int d = 0; d < 64; d++)
            s += qv[d] * (__bfloat162float(Khi[kbase + d]) + __bfloat162float(Klo[kbase + d]));
        float p = expf(s);
        l += p;
        for (int d = 0; d < 64; d++) {
            size_t vi = ((size_t)hk * HD + d) * S_LEN + c;
            o[d] += p * (__bfloat162float(Vthi[vi]) + __bfloat162float(Vtlo[vi]));
        }
    }
    float inv = 1.f / l;
    for (int d = 0; d < 64; d++) {
        float v0 = o[d] * inv;
        __nv_bfloat16 h0 = __float2bfloat16(v0);
        Ohi[(size_t)t * NQD + h * HD + d] = h0;
        Olo[(size_t)t * NQD + h * HD + d] = __float2bfloat16(v0 - __bfloat162float(h0));
    }
#endif
}

// ---------------------------------------------------------------------------
// Launch.
// ---------------------------------------------------------------------------
extern "C" void kernel_launch(void* const* d_in, const int* in_sizes, int n_in,
                              void* d_out, int out_size)
{
    const float* X  = (const float*)d_in[0];
    const float* Wq = (const float*)d_in[1];
    const float* Wk = (const float*)d_in[2];
    const float* Wv = (const float*)d_in[3];
    const float* Wo = (const float*)d_in[4];
    float* out = (float*)d_out;

    float *q, *k, *v;
    cudaGetSymbolAddress((void**)&q, g_q);
    cudaGetSymbolAddress((void**)&k, g_k);
    cudaGetSymbolAddress((void**)&v, g_v);

    __nv_bfloat16 *xhi, *xlo, *chi, *clo;
    __nv_bfloat16 *wqh, *wql, *wkh, *wkl, *wvh, *wvl, *woh, *wol;
    __nv_bfloat16 *qsh, *qsl, *ksh, *ksl, *vth, *vtl;
    cudaGetSymbolAddress((void**)&xhi, g_xhi); cudaGetSymbolAddress((void**)&xlo, g_xlo);
    cudaGetSymbolAddress((void**)&chi, g_chi); cudaGetSymbolAddress((void**)&clo, g_clo);
    cudaGetSymbolAddress((void**)&wqh, g_wqhi); cudaGetSymbolAddress((void**)&wql, g_wqlo);
    cudaGetSymbolAddress((void**)&wkh, g_wkhi); cudaGetSymbolAddress((void**)&wkl, g_wklo);
    cudaGetSymbolAddress((void**)&wvh, g_wvhi); cudaGetSymbolAddress((void**)&wvl, g_wvlo);
    cudaGetSymbolAddress((void**)&woh, g_wohi); cudaGetSymbolAddress((void**)&wol, g_wolo);
    cudaGetSymbolAddress((void**)&qsh, g_qshi); cudaGetSymbolAddress((void**)&qsl, g_qslo);
    cudaGetSymbolAddress((void**)&ksh, g_kshi); cudaGetSymbolAddress((void**)&ksl, g_kslo);
    cudaGetSymbolAddress((void**)&vth, g_vthi); cudaGetSymbolAddress((void**)&vtl, g_vtlo);

    cudaFuncSetAttribute(tc_gemm_kernel,     cudaFuncAttributeMaxDynamicSharedMemorySize, GEMM_SMEM);
    cudaFuncSetAttribute(tc_gemm_qkv_kernel, cudaFuncAttributeMaxDynamicSharedMemorySize, GEMM_SMEM);
    cudaFuncSetAttribute(attn_tc_kernel,     cudaFuncAttributeMaxDynamicSharedMemorySize, ATT_SMEM);

    // 0-4: tables + operand conversions
    rope_table_kernel<<<(S_LEN * 32 + 255) / 256, 256>>>();
    convert_split_kernel<<<(S_LEN * HIDDEN / 4 + 255) / 256, 256>>>(
        (const float4*)X, (uint2*)xhi, (uint2*)xlo, S_LEN * HIDDEN / 4);
    convert_wT_kernel<<<dim3(NQD  / 32, HIDDEN / 32), dim3(32, 8)>>>(Wq, wqh, wql, HIDDEN, NQD);
    convert_wT_kernel<<<dim3(NKVD / 32, HIDDEN / 32), dim3(32, 8)>>>(Wk, wkh, wkl, HIDDEN, NKVD);
    convert_wT_kernel<<<dim3(NKVD / 32, HIDDEN / 32), dim3(32, 8)>>>(Wv, wvh, wvl, HIDDEN, NKVD);

    // 5: fused QKV projections (all fp32 outputs — one launch, 384 CTAs)
    tc_gemm_qkv_kernel<<<dim3(24, S_LEN / 128), 256, GEMM_SMEM>>>(
        xhi, xlo, wqh, wql, wkh, wkl, wvh, wvl, q, k, v);

    // 6-9: attention operand prep (R15-proven vectorized) + Wo conversion
    prep_rope_split_kernel<<<(S_LEN * NQD / 8 + 255) / 256, 256>>>(
        (const float4*)q, (uint4*)qsh, (uint4*)qsl, NQD, 0.125f, S_LEN * NQD / 8);
    prep_rope_split_kernel<<<(S_LEN * NKVD / 8 + 255) / 256, 256>>>(
        (const float4*)k, (uint4*)ksh, (uint4*)ksl, NKVD, 1.0f, S_LEN * NKVD / 8);
    prep_vt_kernel<<<dim3(NKVD / 32, S_LEN / 32), dim3(32, 8)>>>(v, vth, vtl);
    convert_wT_kernel<<<dim3(HIDDEN / 32, NQD / 32), dim3(32, 8)>>>(Wo, woh, wol, NQD, HIDDEN);

    // 10: attention
    attn_tc_kernel<<<dim3(S_LEN / 128, NH), 256, ATT_SMEM>>>(
        qsh, qsl, ksh, ksl, vth, vtl, chi, clo);

    // 11: output projection
    tc_gemm_kernel<<<dim3(HIDDEN / 128, S_LEN / 128), 256, GEMM_SMEM>>>(
        chi, clo, woh, wol, out, S_LEN, HIDDEN, NQD);
}